// round 14
// baseline (speedup 1.0000x reference)
#include <cuda_runtime.h>

#define NB 2
#define NN 192
#define NF 5
#define NSPLIT 2
#define THREADS 192
#define NWARP 6
#define NGRP (NSPLIT*NWARP)   // 12 tile groups
#define NTILE (NN/4)          // 48 tiles of 4 rows

__device__ float g_part[NB * NN * NSPLIT * NF];
__device__ int   g_cnt[NB * NN];          // zero-init; self-resetting

__device__ __forceinline__ float ex2f(float x) {
    float y;
    asm("ex2.approx.ftz.f32 %0, %1;" : "=f"(y) : "f"(x));
    return y;
}

__global__ __launch_bounds__(THREADS, 5)
void fa_kernel(const float* __restrict__ d, const float* __restrict__ cd,
               const float* __restrict__ fp, const float* __restrict__ coeff,
               float* __restrict__ out)
{
    const int blk  = blockIdx.x;
    const int bi   = blk >> 1;            // b*NN + i
    const int c    = blk & 1;
    const int b    = bi / NN;
    const int i    = bi - b * NN;
    const int tid  = threadIdx.x;
    const int lane = tid & 31;
    const int w    = tid >> 5;

    __shared__ float4 sP[NN];        // (d^2, 1/(sqrt2*d), sqrt2*cd0, 0); zeroed at ==i
    __shared__ float  sFp[NF], sC2[NF];
    __shared__ float  sRed[NWARP * NF];
    __shared__ float  sS[NWARP], sSS[NWARP];
    __shared__ float  sCdii;
    __shared__ int    sTicket;

    if (tid < NF) {
        sFp[tid] = fp[tid];
        sC2[tid] = -144.26950408889634f * coeff[tid];   // -100*log2(e)*coeff
    }

    const float* __restrict__ drow  = d  + ((size_t)b * NN + i) * NN;
    const float* __restrict__ cdrow = cd + ((size_t)b * NN + i) * NN;

    // ---- Phase 1: per-k precompute + S/SS partials (192 threads == NN) ----
    {
        float dv = drow[tid];
        float cv = cdrow[tid];
        float c0 = (cv == 1.0f) ? 0.0f : cv;
        float pS = c0, pSS = c0 * c0;
        bool isI = (tid == i);
        float rh = isI ? 0.0f : 0.70710678118654752f / dv;
        float wq = isI ? 0.0f : 1.41421356237309515f * c0;
        sP[tid] = make_float4(dv * dv, rh, wq, 0.0f);
        if (isI) sCdii = c0;
        #pragma unroll
        for (int o = 16; o; o >>= 1) {
            pS  += __shfl_down_sync(0xFFFFFFFFu, pS,  o);
            pSS += __shfl_down_sync(0xFFFFFFFFu, pSS, o);
        }
        if (lane == 0) { sS[w] = pS; sSS[w] = pSS; }
    }
    __syncthreads();

    float c2r[NF], mr[NF], qr[NF], acc[NF];
    #pragma unroll
    for (int f = 0; f < NF; f++) {
        float fpv = sFp[f], c2 = sC2[f];
        c2r[f] = c2;
        mr[f]  = -2.0f * c2 * fpv;
        qr[f]  = c2 * fpv * fpv;
        acc[f] = 0.0f;
    }

    // ---- Phase 2: 4-row register-blocked triangle sweep, balanced tiles ----
    // Tile t = rows 4t..4t+3 costs T(t) = 1 + t/8 warp-iters; T(t)+T(47-t) = 7.
    // Group g gets tiles {g, g+12, 35-g, 47-g}: exactly 14 iters per group.
    const float* __restrict__ dmat = d + (size_t)b * NN * NN;
    const int g = c * NWARP + w;          // 0..11

    #pragma unroll
    for (int s = 0; s < 4; s++) {
        const int t = (s == 0) ? g
                    : (s == 1) ? g + 12
                    : (s == 2) ? 35 - g
                    :            47 - g;
        const int k0 = t << 2;

        float4 Pk[4];
        #pragma unroll
        for (int q = 0; q < 4; q++) Pk[q] = sP[k0 + q];

        const int T = (k0 + 34) >> 5;   // covers j <= k0+2
        const int F = k0 >> 5;          // m < F: fully inside triangle

        const float*  pg = dmat + (size_t)k0 * NN + lane;   // advancing row base
        const float4* ps = sP + lane;                       // advancing table ptr

        float dv[4];
        dv[0] = __ldg(pg);
        dv[1] = __ldg(pg + NN);
        dv[2] = __ldg(pg + 2 * NN);
        dv[3] = __ldg(pg + 3 * NN);
        float4 Pj = *ps;

        for (int m = 0; m < T; m++) {
            float ev[4];
            #pragma unroll
            for (int q = 0; q < 4; q++) ev[q] = dv[q];
            float4 Pc = Pj;

            if (m + 1 < T) {                  // prefetch next chunk
                pg += 32; ps += 32;
                dv[0] = __ldg(pg);
                dv[1] = __ldg(pg + NN);
                dv[2] = __ldg(pg + 2 * NN);
                dv[3] = __ldg(pg + 3 * NN);
                Pj = *ps;
            }

            float av[4], a2v[4], wv[4];
            #pragma unroll
            for (int q = 0; q < 4; q++) {
                float num = fmaf(-ev[q], ev[q], Pk[q].x + Pc.x);
                float a   = (num * Pc.y) * Pk[q].y;
                av[q]  = a;
                a2v[q] = a * a;
                wv[q]  = Pk[q].z * Pc.z;
            }
            if (m >= F) {                     // warp-uniform: single masked iter
                const int jc = lane + (m << 5);
                #pragma unroll
                for (int q = 0; q < 4; q++)
                    wv[q] = (jc < k0 + q) ? wv[q] : 0.0f;
            }

            #pragma unroll
            for (int q = 0; q < 4; q++) {
                #pragma unroll
                for (int f = 0; f < NF; f++) {
                    float arg = fmaf(c2r[f], a2v[q], fmaf(mr[f], av[q], qr[f]));
                    acc[f] = fmaf(ex2f(arg), wv[q], acc[f]);
                }
            }
        }
    }

    // ---- Reduce 5 accumulators within the CTA ----
    #pragma unroll
    for (int f = 0; f < NF; f++) {
        #pragma unroll
        for (int o = 16; o; o >>= 1)
            acc[f] += __shfl_down_sync(0xFFFFFFFFu, acc[f], o);
    }
    if (lane == 0) {
        #pragma unroll
        for (int f = 0; f < NF; f++) sRed[w * NF + f] = acc[f];
    }
    __syncthreads();

    // ---- Publish partial, take ticket; last CTA combines in FIXED order ----
    if (tid < NF) {
        float tacc = 0.f;
        #pragma unroll
        for (int wi = 0; wi < NWARP; wi++) tacc += sRed[wi * NF + tid];
        g_part[(bi * NSPLIT + c) * NF + tid] = tacc;
    }
    __threadfence();
    __syncthreads();
    if (tid == 0) sTicket = atomicAdd(&g_cnt[bi], 1);
    __syncthreads();

    if (sTicket == NSPLIT - 1) {              // last arriver combines
        __threadfence();
        if (tid < NF) {
            float tacc = 0.f;
            #pragma unroll
            for (int s2 = 0; s2 < NSPLIT; s2++)  // fixed order -> deterministic
                tacc += g_part[(bi * NSPLIT + s2) * NF + tid];
            float S = 0.f, SS = 0.f;
            #pragma unroll
            for (int wi = 0; wi < NWARP; wi++) { S += sS[wi]; SS += sSS[wi]; }
            float cii = sCdii;
            float fpv = sFp[tid], c2v = sC2[tid];
            float g0 = ex2f((c2v * fpv) * fpv);        // a = 0 (j==i or k==i)
            float d1 = 1.0f - fpv;
            float g1 = ex2f((c2v * d1) * d1);          // a = 1 (diag j==k!=i)
            tacc += g0 * cii * (2.0f * S - cii) + g1 * (SS - cii * cii);
            out[(size_t)bi * NF + tid] = tacc * (1.0f / (NN * 12));
        }
        if (tid == 0) atomicExch(&g_cnt[bi], 0);   // reset for replay
    }
}

extern "C" void kernel_launch(void* const* d_in, const int* in_sizes, int n_in,
                              void* d_out, int out_size)
{
    const float* d     = (const float*)d_in[0];   // (B,N,N)
    const float* cd    = (const float*)d_in[1];   // (B,N,N)
    const float* fp    = (const float*)d_in[2];   // (5,)
    const float* coeff = (const float*)d_in[3];   // (5,)
    float* out = (float*)d_out;                   // (B,N,5)

    fa_kernel<<<NB * NN * NSPLIT, THREADS>>>(d, cd, fp, coeff, out);
}